// round 12
// baseline (speedup 1.0000x reference)
#include <cuda_runtime.h>
#include <math.h>
#include <stdint.h>

#define NTOK  (8*64*64)

// Scratch (device globals)
__device__ float g_hs[(size_t)NTOK * 224];   // residual + attn output
__device__ float g_w1p[896 * 224];           // tf32 mlp1_w, [h][pk8(k)]
__device__ float g_w2p[224 * 896];           // tf32 mlp2_w, [n][pk8(h)]
__device__ float g_wbigT[896 * 112];         // tf32 [Q|K|V|R] weights, [n][pk8(k)]
__device__ float g_wptT[224 * 224];          // tf32 attn_proj_w, [n][pk8(k)]
__device__ float g_bbig[896];                // [qkv_b | res_proj_b]

__device__ __forceinline__ unsigned f2tf32(float x) {
    unsigned r;
    asm("cvt.rna.tf32.f32 %0, %1;" : "=r"(r) : "f"(x));
    return r;
}
__device__ __forceinline__ float rtf(float x) { return __uint_as_float(f2tf32(x)); }
__device__ __forceinline__ unsigned fu(float x) { return __float_as_uint(x); }

__device__ __forceinline__ int pk8(int k) {
    return (k & ~7) + ((k & 3) << 1) + ((k >> 2) & 1);
}

__device__ __forceinline__ void mma_tf32(float* c,
        unsigned a0, unsigned a1, unsigned a2, unsigned a3,
        unsigned b0, unsigned b1) {
    asm("mma.sync.aligned.m16n8k8.row.col.f32.tf32.tf32.f32 "
        "{%0,%1,%2,%3}, {%4,%5,%6,%7}, {%8,%9}, {%0,%1,%2,%3};"
        : "+f"(c[0]), "+f"(c[1]), "+f"(c[2]), "+f"(c[3])
        : "r"(a0), "r"(a1), "r"(a2), "r"(a3), "r"(b0), "r"(b1));
}

// ---------------------------------------------------------------------------
// K0: tf32-round weights into packed-k transposed layouts + combined bias
// ---------------------------------------------------------------------------
__global__ void k_prep(const float* __restrict__ W1,   const float* __restrict__ W2,
                       const float* __restrict__ Wqkv, const float* __restrict__ Wrp,
                       const float* __restrict__ Wp,
                       const float* __restrict__ bqkv, const float* __restrict__ brp) {
    int i = blockIdx.x * 1024 + threadIdx.x;
    if (i < 224 * 896) {
        int k = i / 896, h = i - k * 896;
        g_w1p[h * 224 + pk8(k)] = rtf(W1[i]);
        int h2 = i / 224, n = i - h2 * 224;
        g_w2p[n * 896 + pk8(h2)] = rtf(W2[i]);
    }
    if (i < 112 * 896) {
        int r = i / 896, c = i - r * 896;
        float v = (c < 672) ? Wqkv[r * 672 + c] : Wrp[r * 224 + (c - 672)];
        g_wbigT[c * 112 + pk8(r)] = rtf(v);
    }
    if (i < 224 * 224) {
        int k = i / 224, n = i - k * 224;
        g_wptT[n * 224 + pk8(k)] = rtf(Wp[i]);
    }
    if (i < 896) g_bbig[i] = (i < 672) ? bqkv[i] : brp[i - 672];
}

// ---------------------------------------------------------------------------
// K3: fused LN1 + QKV/R GEMM + pooling + attention + proj + residual
// 2048 blocks x 448 threads (14 warps)
// smem: Xs[64][136] packed-k | Krow[64][236] | Vrow[64][232] | Qt[16][236]
//       | Rt[16][236] | stats 256
// P (64x76) aliases Xs; Ot (16x232, packed-d) aliases Qt.
// ---------------------------------------------------------------------------
#define XS_STR 136
#define KR_STR 236
#define VR_STR 232
#define QT_STR 236
#define RT_STR 236
#define OT_STR 232
#define P_STR  76
#define XS_N (64 * XS_STR)     // 8704
#define KR_N (64 * KR_STR)     // 15104
#define VR_N (64 * VR_STR)     // 14848
#define QT_N (16 * QT_STR)     // 3776
#define RT_N (16 * RT_STR)     // 3776
#define SMEM3 ((XS_N + KR_N + VR_N + QT_N + RT_N + 256) * 4)   // 185856 B

__global__ void __launch_bounds__(448) k_attn(
        const float* __restrict__ hidden,
        const float* __restrict__ ln1g, const float* __restrict__ ln1b,
        const float* __restrict__ bp) {
    extern __shared__ float sm[];
    float* Xs   = sm;
    float* Krow = Xs + XS_N;
    float* Vrow = Krow + KR_N;
    float* Qt   = Vrow + VR_N;
    float* Rt   = Qt + QT_N;
    float* smax = Rt + RT_N;      // [64][2]
    float* ssum = smax + 128;     // [64][2]
    float* P    = Xs;    // alias (X dead after QKV)
    float* Ot   = Qt;    // alias (Qt dead after scores)

    int wi = blockIdx.x;
    int b  = wi >> 8;
    int r  = wi & 255;
    int wy = r >> 4, wx = r & 15;
    int tid  = threadIdx.x;
    int warp = tid >> 5, lane = tid & 31;
    int g = lane >> 2, tig = lane & 3;

    // ---- stage raw window into packed-k layout ----
    for (int e = tid; e < 64 * 28; e += 448) {
        int t = e / 28, c4 = (e - t * 28) * 4;
        int y = wy * 8 + (t >> 3), x = wx * 8 + (t & 7);
        float4 v = *(const float4*)&hidden[(((size_t)b * 128 + y) * 128 + x) * 112 + c4];
        int off = t * XS_STR + (c4 & ~7) + ((c4 >> 2) & 1);
        Xs[off + 0] = v.x; Xs[off + 2] = v.y; Xs[off + 4] = v.z; Xs[off + 6] = v.w;
    }
    __syncthreads();

    // ---- LN1 in place (warp per token), tf32-rounded; packed indices ----
    {
        int pl = pk8(lane);
        float gg0 = ln1g[lane], gg1 = ln1g[lane + 32], gg2 = ln1g[lane + 64];
        float bb0 = ln1b[lane], bb1 = ln1b[lane + 32], bb2 = ln1b[lane + 64];
        float gg3 = 0.f, bb3 = 0.f;
        if (lane < 16) { gg3 = ln1g[lane + 96]; bb3 = ln1b[lane + 96]; }
        for (int t = warp; t < 64; t += 14) {
            float* row = Xs + t * XS_STR;
            float v0 = row[pl], v1 = row[pl + 32], v2 = row[pl + 64];
            float v3 = (lane < 16) ? row[pl + 96] : 0.f;
            float s = v0 + v1 + v2 + v3;
            #pragma unroll
            for (int o = 16; o; o >>= 1) s += __shfl_xor_sync(~0u, s, o);
            float m = s * (1.f / 112.f);
            float d0 = v0 - m, d1 = v1 - m, d2 = v2 - m;
            float d3 = (lane < 16) ? v3 - m : 0.f;
            float q = d0*d0 + d1*d1 + d2*d2 + d3*d3;
            #pragma unroll
            for (int o = 16; o; o >>= 1) q += __shfl_xor_sync(~0u, q, o);
            float rs = rsqrtf(q * (1.f / 112.f) + 1e-6f);
            row[pl]      = rtf(d0 * rs * gg0 + bb0);
            row[pl + 32] = rtf(d1 * rs * gg1 + bb1);
            row[pl + 64] = rtf(d2 * rs * gg2 + bb2);
            if (lane < 16) row[pl + 96] = rtf(d3 * rs * gg3 + bb3);
        }
    }
    __syncthreads();

    // ---- QKV+R GEMM: M=64, N=896, K=112; float2 fragment loads ----
    {
        #pragma unroll
        for (int pass = 0; pass < 2; pass++) {
            int colbase = warp * 64 + pass * 32;
            float acc[4][4][4];
            #pragma unroll
            for (int j = 0; j < 4; j++) {
                int col = colbase + j * 8;
                float bv0 = g_bbig[col + 2 * tig];
                float bv1 = g_bbig[col + 2 * tig + 1];
                #pragma unroll
                for (int mt = 0; mt < 4; mt++) {
                    acc[mt][j][0] = bv0; acc[mt][j][1] = bv1;
                    acc[mt][j][2] = bv0; acc[mt][j][3] = bv1;
                }
            }
            for (int kc = 0; kc < 112; kc += 8) {
                float2 aA[4][2];
                #pragma unroll
                for (int mt = 0; mt < 4; mt++) {
                    int r0 = (mt * 16 + g) * XS_STR + kc + 2 * tig;
                    aA[mt][0] = *(const float2*)&Xs[r0];
                    aA[mt][1] = *(const float2*)&Xs[r0 + 8 * XS_STR];
                }
                #pragma unroll
                for (int j = 0; j < 4; j++) {
                    int col = colbase + j * 8 + g;
                    float2 bv = *(const float2*)&g_wbigT[col * 112 + kc + 2 * tig];
                    #pragma unroll
                    for (int mt = 0; mt < 4; mt++)
                        mma_tf32(acc[mt][j], fu(aA[mt][0].x), fu(aA[mt][1].x),
                                 fu(aA[mt][0].y), fu(aA[mt][1].y), fu(bv.x), fu(bv.y));
                }
            }
            // routed stores (uniform branch per warp/j); K and V row-major float2
            #pragma unroll
            for (int j = 0; j < 4; j++) {
                int col = colbase + j * 8;
                int mat = col / 224;
                int lc  = col - mat * 224;
                if (mat == 1 || mat == 2) {   // K or V -> row-major [t][d]
                    float* dst = (mat == 1) ? Krow : Vrow;
                    int str    = (mat == 1) ? KR_STR : VR_STR;
                    #pragma unroll
                    for (int mt = 0; mt < 4; mt++) {
                        int t0r = mt * 16 + g;
                        *(float2*)&dst[t0r * str + lc + 2*tig] =
                            make_float2(rtf(acc[mt][j][0]), rtf(acc[mt][j][1]));
                        *(float2*)&dst[(t0r + 8) * str + lc + 2*tig] =
                            make_float2(rtf(acc[mt][j][2]), rtf(acc[mt][j][3]));
                    }
                } else {                      // Q (mat 0) or R (mat 3): 2x2 pool in regs
                    #pragma unroll
                    for (int mt = 0; mt < 4; mt++) {
                        float m0 = fmaxf(acc[mt][j][0], acc[mt][j][2]);  // rows g, g+8
                        float m1 = fmaxf(acc[mt][j][1], acc[mt][j][3]);
                        m0 = fmaxf(m0, __shfl_xor_sync(~0u, m0, 4));     // lanes g ^ 1
                        m1 = fmaxf(m1, __shfl_xor_sync(~0u, m1, 4));
                        if (!(g & 1)) {
                            int q = mt * 4 + (g >> 1);
                            if (mat == 0)
                                *(float2*)&Qt[q * QT_STR + lc + 2*tig] =
                                    make_float2(rtf(m0), rtf(m1));
                            else
                                *(float2*)&Rt[q * RT_STR + lc + 2*tig] =
                                    make_float2(m0, m1);
                        }
                    }
                }
            }
        }
    }
    __syncthreads();

    // ---- scores + in-register softmax (8 warps) -> P (aliases Xs) ----
    const float scale = 0.13363062095621219f;   // 56^-0.5
    bool sa = (warp < 8);
    int sh = warp >> 1, snh = warp & 1;
    float sc[4][4];
    if (sa) {
        const unsigned* Qb = (const unsigned*)Qt;
        const unsigned* Kb = (const unsigned*)Krow;
        #pragma unroll
        for (int j = 0; j < 4; j++)
            #pragma unroll
            for (int e = 0; e < 4; e++) sc[j][e] = 0.f;
        #pragma unroll
        for (int kc = 0; kc < 56; kc += 8) {
            int kd = sh * 56 + kc;
            unsigned a0 = Qb[g * QT_STR + kd + tig];
            unsigned a1 = Qb[(g + 8) * QT_STR + kd + tig];
            unsigned a2 = Qb[g * QT_STR + kd + tig + 4];
            unsigned a3 = Qb[(g + 8) * QT_STR + kd + tig + 4];
            #pragma unroll
            for (int j = 0; j < 4; j++) {
                int n0 = snh * 32 + j * 8;
                unsigned b0 = Kb[(n0 + g) * KR_STR + kd + tig];
                unsigned b1 = Kb[(n0 + g) * KR_STR + kd + tig + 4];
                mma_tf32(sc[j], a0, a1, a2, a3, b0, b1);
            }
        }
        float m0 = -1e30f, m1 = -1e30f;
        #pragma unroll
        for (int j = 0; j < 4; j++) {
            sc[j][0] *= scale; sc[j][1] *= scale;
            sc[j][2] *= scale; sc[j][3] *= scale;
            m0 = fmaxf(m0, fmaxf(sc[j][0], sc[j][1]));
            m1 = fmaxf(m1, fmaxf(sc[j][2], sc[j][3]));
        }
        m0 = fmaxf(m0, __shfl_xor_sync(~0u, m0, 1));
        m0 = fmaxf(m0, __shfl_xor_sync(~0u, m0, 2));
        m1 = fmaxf(m1, __shfl_xor_sync(~0u, m1, 1));
        m1 = fmaxf(m1, __shfl_xor_sync(~0u, m1, 2));
        if (tig == 0) {
            smax[(sh * 16 + g) * 2 + snh]     = m0;
            smax[(sh * 16 + g + 8) * 2 + snh] = m1;
        }
    }
    __syncthreads();
    if (sa) {
        int r0 = sh * 16 + g, r1 = r0 + 8;
        float M0 = fmaxf(smax[r0 * 2], smax[r0 * 2 + 1]);
        float M1 = fmaxf(smax[r1 * 2], smax[r1 * 2 + 1]);
        float s0 = 0.f, s1 = 0.f;
        #pragma unroll
        for (int j = 0; j < 4; j++) {
            sc[j][0] = __expf(sc[j][0] - M0); sc[j][1] = __expf(sc[j][1] - M0);
            sc[j][2] = __expf(sc[j][2] - M1); sc[j][3] = __expf(sc[j][3] - M1);
            s0 += sc[j][0] + sc[j][1];
            s1 += sc[j][2] + sc[j][3];
        }
        s0 += __shfl_xor_sync(~0u, s0, 1); s0 += __shfl_xor_sync(~0u, s0, 2);
        s1 += __shfl_xor_sync(~0u, s1, 1); s1 += __shfl_xor_sync(~0u, s1, 2);
        if (tig == 0) {
            ssum[r0 * 2 + snh] = s0;
            ssum[r1 * 2 + snh] = s1;
        }
    }
    __syncthreads();
    if (sa) {
        int r0 = sh * 16 + g, r1 = r0 + 8;
        float inv0 = 1.f / (ssum[r0 * 2] + ssum[r0 * 2 + 1]);
        float inv1 = 1.f / (ssum[r1 * 2] + ssum[r1 * 2 + 1]);
        #pragma unroll
        for (int j = 0; j < 4; j++) {
            int n0 = snh * 32 + j * 8;
            *(float2*)&P[r0 * P_STR + n0 + 2*tig] =
                make_float2(rtf(sc[j][0] * inv0), rtf(sc[j][1] * inv0));
            *(float2*)&P[r1 * P_STR + n0 + 2*tig] =
                make_float2(rtf(sc[j][2] * inv1), rtf(sc[j][3] * inv1));
        }
    }
    __syncthreads();

    // ---- PV: per head 16x56x64 -> Ot (packed-d, aliases Qt) ----
    {
        const unsigned* Pb = (const unsigned*)P;
        const unsigned* Vb = (const unsigned*)Vrow;
        #pragma unroll
        for (int ui = 0; ui < 2; ui++) {
            int u = warp * 2 + ui;        // 0..27
            int h = u / 7, j = u - h * 7;
            int n0 = h * 56 + j * 8;
            float acc[4] = {0.f, 0.f, 0.f, 0.f};
            #pragma unroll
            for (int kc = 0; kc < 64; kc += 8) {
                unsigned a0 = Pb[(h * 16 + g) * P_STR + kc + tig];
                unsigned a1 = Pb[(h * 16 + g + 8) * P_STR + kc + tig];
                unsigned a2 = Pb[(h * 16 + g) * P_STR + kc + tig + 4];
                unsigned a3 = Pb[(h * 16 + g + 8) * P_STR + kc + tig + 4];
                unsigned b0 = Vb[(kc + tig) * VR_STR + n0 + g];
                unsigned b1 = Vb[(kc + tig + 4) * VR_STR + n0 + g];
                mma_tf32(acc, a0, a1, a2, a3, b0, b1);
            }
            int p0 = pk8(n0 + 2 * tig);
            int p1 = pk8(n0 + 2 * tig + 1);
            Ot[g * OT_STR + p0]       = rtf(acc[0]);
            Ot[g * OT_STR + p1]       = rtf(acc[1]);
            Ot[(g + 8) * OT_STR + p0] = rtf(acc[2]);
            Ot[(g + 8) * OT_STR + p1] = rtf(acc[3]);
        }
    }
    __syncthreads();

    // ---- attn_proj (16x224x224), float2 fragment loads, accumulate into Rt ----
    {
        int n0w = warp * 16;
        float acc[2][4];
        #pragma unroll
        for (int j = 0; j < 2; j++) {
            int col = n0w + j * 8;
            float bv0 = bp[col + 2 * tig];
            float bv1 = bp[col + 2 * tig + 1];
            acc[j][0] = bv0; acc[j][1] = bv1; acc[j][2] = bv0; acc[j][3] = bv1;
        }
        #pragma unroll 4
        for (int kc = 0; kc < 224; kc += 8) {
            int r0 = g * OT_STR + kc + 2 * tig;
            float2 A0 = *(const float2*)&Ot[r0];
            float2 A1 = *(const float2*)&Ot[r0 + 8 * OT_STR];
            #pragma unroll
            for (int j = 0; j < 2; j++) {
                int col = n0w + j * 8 + g;
                float2 bv = *(const float2*)&g_wptT[col * 224 + kc + 2 * tig];
                mma_tf32(acc[j], fu(A0.x), fu(A1.x), fu(A0.y), fu(A1.y),
                         fu(bv.x), fu(bv.y));
            }
        }
        #pragma unroll
        for (int j = 0; j < 2; j++) {
            int d = n0w + j * 8 + 2 * tig;
            float2 r0v = *(float2*)&Rt[g * RT_STR + d];
            *(float2*)&Rt[g * RT_STR + d] =
                make_float2(r0v.x + acc[j][0], r0v.y + acc[j][1]);
            float2 r1v = *(float2*)&Rt[(g + 8) * RT_STR + d];
            *(float2*)&Rt[(g + 8) * RT_STR + d] =
                make_float2(r1v.x + acc[j][2], r1v.y + acc[j][3]);
        }
    }
    __syncthreads();

    // ---- coalesced writeout of hs = residual + proj ----
    for (int e = tid; e < 16 * 56; e += 448) {
        int q = e / 56, c4 = (e - q * 56) * 4;
        int y2 = wy * 4 + (q >> 2), x2 = wx * 4 + (q & 3);
        *(float4*)&g_hs[(((size_t)b * 64 + y2) * 64 + x2) * 224 + c4] =
            *(float4*)&Rt[q * RT_STR + c4];
    }
}

// ---------------------------------------------------------------------------
// K4: out = hs + MLP(LN2(hs)); 512 blocks x 448 threads; packed-k layouts.
// smem: Xln[64][232] packed-c | Ha[64][456] packed-h
// ---------------------------------------------------------------------------
#define XLN_STR 232
#define HA_STR  456
#define SMEM4   ((64 * XLN_STR + 64 * HA_STR) * 4)   // 176128 B

__global__ void __launch_bounds__(448) k_mlp(
        const float* __restrict__ g2, const float* __restrict__ b2,
        const float* __restrict__ b1, const float* __restrict__ b2m,
        float* __restrict__ out) {
    extern __shared__ float sm[];
    float* Xln = sm;
    float* Ha  = sm + 64 * XLN_STR;

    int t0   = blockIdx.x * 64;
    int tid  = threadIdx.x;
    int warp = tid >> 5, lane = tid & 31;
    int g = lane >> 2, tig = lane & 3;

    // ---- LN2 (warp per token) -> Xln packed-c tf32 ----
    {
        int pl = pk8(lane);
        float gv[7], bv[7];
        #pragma unroll
        for (int k = 0; k < 7; k++) { gv[k] = g2[lane + 32*k]; bv[k] = b2[lane + 32*k]; }
        for (int t = warp; t < 64; t += 14) {
            const float* hr = &g_hs[(size_t)(t0 + t) * 224];
            float v[7]; float s = 0.f;
            #pragma unroll
            for (int k = 0; k < 7; k++) { v[k] = hr[lane + 32*k]; s += v[k]; }
            #pragma unroll
            for (int o = 16; o; o >>= 1) s += __shfl_xor_sync(~0u, s, o);
            float m = s * (1.f / 224.f);
            float q = 0.f;
            #pragma unroll
            for (int k = 0; k < 7; k++) { v[k] -= m; q += v[k] * v[k]; }
            #pragma unroll
            for (int o = 16; o; o >>= 1) q += __shfl_xor_sync(~0u, q, o);
            float rs = rsqrtf(q * (1.f / 224.f) + 1e-6f);
            #pragma unroll
            for (int k = 0; k < 7; k++)
                Xln[t * XLN_STR + pl + 32*k] = rtf(v[k] * rs * gv[k] + bv[k]);
        }
    }
    __syncthreads();

    int n0w = warp * 16;
    float acc2[4][2][4];
    #pragma unroll
    for (int j = 0; j < 2; j++) {
        float bv0 = b2m[n0w + j * 8 + 2 * tig];
        float bv1 = b2m[n0w + j * 8 + 2 * tig + 1];
        #pragma unroll
        for (int mt = 0; mt < 4; mt++) {
            acc2[mt][j][0] = bv0; acc2[mt][j][1] = bv1;
            acc2[mt][j][2] = bv0; acc2[mt][j][3] = bv1;
        }
    }

    #pragma unroll 1
    for (int hp = 0; hp < 2; hp++) {
        int hb = hp * 448;
        // ---- MLP1: warp cols = hb + warp*32 .. +32, all 64 rows ----
        {
            int cb = hb + warp * 32;
            float acc1[4][4][4];
            #pragma unroll
            for (int j = 0; j < 4; j++) {
                float bv0 = b1[cb + j * 8 + 2 * tig];
                float bv1 = b1[cb + j * 8 + 2 * tig + 1];
                #pragma unroll
                for (int mt = 0; mt < 4; mt++) {
                    acc1[mt][j][0] = bv0; acc1[mt][j][1] = bv1;
                    acc1[mt][j][2] = bv0; acc1[mt][j][3] = bv1;
                }
            }
            for (int kc = 0; kc < 224; kc += 8) {
                float2 aA[4][2];
                #pragma unroll
                for (int mt = 0; mt < 4; mt++) {
                    int r0 = (mt * 16 + g) * XLN_STR + kc + 2 * tig;
                    aA[mt][0] = *(const float2*)&Xln[r0];
                    aA[mt][1] = *(const float2*)&Xln[r0 + 8 * XLN_STR];
                }
                #pragma unroll
                for (int j = 0; j < 4; j++) {
                    int col = cb + j * 8 + g;
                    float2 wv = *(const float2*)&g_w1p[col * 224 + kc + 2 * tig];
                    #pragma unroll
                    for (int mt = 0; mt < 4; mt++)
                        mma_tf32(acc1[mt][j], fu(aA[mt][0].x), fu(aA[mt][1].x),
                                 fu(aA[mt][0].y), fu(aA[mt][1].y), fu(wv.x), fu(wv.y));
                }
            }
            // GELU -> Ha packed-h (scalar stores)
            int lb = warp * 32;
            #pragma unroll
            for (int mt = 0; mt < 4; mt++)
                #pragma unroll
                for (int j = 0; j < 4; j++) {
                    int lh0 = lb + j * 8 + 2 * tig;
                    int p0 = pk8(lh0), p1 = pk8(lh0 + 1);
                    int m0 = mt * 16 + g;
                    float a0 = acc1[mt][j][0], a1 = acc1[mt][j][1];
                    float a2 = acc1[mt][j][2], a3 = acc1[mt][j][3];
                    Ha[m0 * HA_STR + p0] =
                        rtf(0.5f * a0 * (1.f + erff(a0 * 0.70710678118654752f)));
                    Ha[m0 * HA_STR + p1] =
                        rtf(0.5f * a1 * (1.f + erff(a1 * 0.70710678118654752f)));
                    Ha[(m0 + 8) * HA_STR + p0] =
                        rtf(0.5f * a2 * (1.f + erff(a2 * 0.70710678118654752f)));
                    Ha[(m0 + 8) * HA_STR + p1] =
                        rtf(0.5f * a3 * (1.f + erff(a3 * 0.70710678118654752f)));
                }
        }
        __syncthreads();
        // ---- MLP2 partial over this half (K=448), float2 fragment loads ----
        for (int kc = 0; kc < 448; kc += 8) {
            float2 aA[4][2];
            #pragma unroll
            for (int mt = 0; mt < 4; mt++) {
                int r0 = (mt * 16 + g) * HA_STR + kc + 2 * tig;
                aA[mt][0] = *(const float2*)&Ha[r0];
                aA[mt][1] = *(const float2*)&Ha[r0 + 8 * HA_STR];
            }
            #pragma unroll
            for (int j = 0; j < 2; j++) {
                int col = n0w + j * 8 + g;
                float2 wv = *(const float2*)&g_w2p[col * 896 + hb + kc + 2 * tig];
                #pragma unroll
                for (int mt = 0; mt < 4; mt++)
                    mma_tf32(acc2[mt][j], fu(aA[mt][0].x), fu(aA[mt][1].x),
                             fu(aA[mt][0].y), fu(aA[mt][1].y), fu(wv.x), fu(wv.y));
            }
        }
        __syncthreads();
    }

    // ---- epilogue: residual + direct store (float2 row segments) ----
    #pragma unroll
    for (int mt = 0; mt < 4; mt++)
        #pragma unroll
        for (int j = 0; j < 2; j++) {
            int n = n0w + j * 8 + 2 * tig;
            int m0 = t0 + mt * 16 + g;
            float2 h0 = *(const float2*)&g_hs[(size_t)m0 * 224 + n];
            *(float2*)&out[(size_t)m0 * 224 + n] =
                make_float2(h0.x + acc2[mt][j][0], h0.y + acc2[mt][j][1]);
            float2 h1 = *(const float2*)&g_hs[(size_t)(m0 + 8) * 224 + n];
            *(float2*)&out[(size_t)(m0 + 8) * 224 + n] =
                make_float2(h1.x + acc2[mt][j][2], h1.y + acc2[mt][j][3]);
        }
}

// ---------------------------------------------------------------------------
extern "C" void kernel_launch(void* const* d_in, const int* in_sizes, int n_in,
                              void* d_out, int out_size) {
    const float* hidden   = (const float*)d_in[0];
    const float* ln1_g    = (const float*)d_in[1];
    const float* ln1_b    = (const float*)d_in[2];
    const float* qkv_w    = (const float*)d_in[3];
    const float* qkv_b    = (const float*)d_in[4];
    const float* aproj_w  = (const float*)d_in[5];
    const float* aproj_b  = (const float*)d_in[6];
    const float* rproj_w  = (const float*)d_in[7];
    const float* rproj_b  = (const float*)d_in[8];
    const float* ln2_g    = (const float*)d_in[9];
    const float* ln2_b    = (const float*)d_in[10];
    const float* mlp1_w   = (const float*)d_in[11];
    const float* mlp1_b   = (const float*)d_in[12];
    const float* mlp2_w   = (const float*)d_in[13];
    const float* mlp2_b   = (const float*)d_in[14];
    float* out = (float*)d_out;

    cudaFuncSetAttribute(k_attn, cudaFuncAttributeMaxDynamicSharedMemorySize, SMEM3);
    cudaFuncSetAttribute(k_mlp,  cudaFuncAttributeMaxDynamicSharedMemorySize, SMEM4);

    k_prep<<<196, 1024>>>(mlp1_w, mlp2_w, qkv_w, rproj_w, aproj_w, qkv_b, rproj_b);
    k_attn<<<2048, 448, SMEM3>>>(hidden, ln1_g, ln1_b, aproj_b);
    k_mlp<<<512, 448, SMEM4>>>(ln2_g, ln2_b, mlp1_b, mlp2_b, out);
}

// round 14
// speedup vs baseline: 1.0918x; 1.0918x over previous
#include <cuda_runtime.h>
#include <math.h>
#include <stdint.h>

#define NTOK  (8*64*64)

// Scratch (device globals)
__device__ float g_hs[(size_t)NTOK * 224];   // residual + attn output
__device__ float g_w1t[224 * 896];           // tf32 mlp1_w
__device__ float g_w2t[896 * 224];           // tf32 mlp2_w
__device__ float g_wbig[112 * 896];          // tf32 [qkv_w | res_proj_w]
__device__ float g_wpt[224 * 224];           // tf32 attn_proj_w
__device__ float g_bbig[896];                // [qkv_b | res_proj_b]

__device__ __forceinline__ unsigned f2tf32(float x) {
    unsigned r;
    asm("cvt.rna.tf32.f32 %0, %1;" : "=r"(r) : "f"(x));
    return r;
}
__device__ __forceinline__ float rtf(float x) { return __uint_as_float(f2tf32(x)); }

__device__ __forceinline__ void mma_tf32(float* c,
        unsigned a0, unsigned a1, unsigned a2, unsigned a3,
        unsigned b0, unsigned b1) {
    asm("mma.sync.aligned.m16n8k8.row.col.f32.tf32.tf32.f32 "
        "{%0,%1,%2,%3}, {%4,%5,%6,%7}, {%8,%9}, {%0,%1,%2,%3};"
        : "+f"(c[0]), "+f"(c[1]), "+f"(c[2]), "+f"(c[3])
        : "r"(a0), "r"(a1), "r"(a2), "r"(a3), "r"(b0), "r"(b1));
}

// ---------------------------------------------------------------------------
// K0: round weights to tf32, build combined [qkv|res] weight + bias
// ---------------------------------------------------------------------------
__global__ void k_prep(const float* __restrict__ W1,   const float* __restrict__ W2,
                       const float* __restrict__ Wqkv, const float* __restrict__ Wrp,
                       const float* __restrict__ Wp,
                       const float* __restrict__ bqkv, const float* __restrict__ brp) {
    int i = blockIdx.x * 1024 + threadIdx.x;
    if (i < 224 * 896) { g_w1t[i] = rtf(W1[i]); g_w2t[i] = rtf(W2[i]); }
    if (i < 112 * 896) {
        int r = i / 896, c = i - r * 896;
        float v = (c < 672) ? Wqkv[r * 672 + c] : Wrp[r * 224 + (c - 672)];
        g_wbig[i] = rtf(v);
    }
    if (i < 224 * 224) g_wpt[i] = rtf(Wp[i]);
    if (i < 896) g_bbig[i] = (i < 672) ? bqkv[i] : brp[i - 672];
}

// ---------------------------------------------------------------------------
// K3: fused LN1 + QKV/R GEMM + pooling + attention + proj + residual
// 2048 blocks x 448 threads (14 warps)
// smem: Xs[64][116] | Krow[64][236] | Vrow[64][232] | Qt[16][236] | Rt[16][236]
//       | stats 256
// P (64x76) aliases Xs; Ot (16x236) aliases Qt.
// ---------------------------------------------------------------------------
#define XS_STR 116
#define KR_STR 236
#define VR_STR 232
#define QT_STR 236
#define RT_STR 236
#define OT_STR 236
#define P_STR  76
#define XS_N (64 * XS_STR)     // 7424
#define KR_N (64 * KR_STR)     // 15104
#define VR_N (64 * VR_STR)     // 14848
#define QT_N (16 * QT_STR)     // 3776
#define RT_N (16 * RT_STR)     // 3776
#define SMEM3 ((XS_N + KR_N + VR_N + QT_N + RT_N + 256) * 4)   // 180736 B

__global__ void __launch_bounds__(448) k_attn(
        const float* __restrict__ hidden,
        const float* __restrict__ ln1g, const float* __restrict__ ln1b,
        const float* __restrict__ bp) {
    extern __shared__ float sm[];
    float* Xs   = sm;
    float* Krow = Xs + XS_N;
    float* Vrow = Krow + KR_N;
    float* Qt   = Vrow + VR_N;
    float* Rt   = Qt + QT_N;
    float* smax = Rt + RT_N;      // [64][2]
    float* ssum = smax + 128;     // [64][2]
    float* P    = Xs;    // alias (X dead after QKV)
    float* Ot   = Qt;    // alias (Qt dead after scores)

    int wi = blockIdx.x;
    int b  = wi >> 8;
    int r  = wi & 255;
    int wy = r >> 4, wx = r & 15;
    int tid  = threadIdx.x;
    int warp = tid >> 5, lane = tid & 31;
    int g = lane >> 2, tig = lane & 3;

    // ---- stage raw window ----
    for (int e = tid; e < 64 * 28; e += 448) {
        int t = e / 28, c4 = (e - t * 28) * 4;
        int y = wy * 8 + (t >> 3), x = wx * 8 + (t & 7);
        *(float4*)&Xs[t * XS_STR + c4] =
            *(const float4*)&hidden[(((size_t)b * 128 + y) * 128 + x) * 112 + c4];
    }
    __syncthreads();

    // ---- LN1 in place (warp per token), tf32-rounded ----
    {
        float gg0 = ln1g[lane], gg1 = ln1g[lane + 32], gg2 = ln1g[lane + 64];
        float bb0 = ln1b[lane], bb1 = ln1b[lane + 32], bb2 = ln1b[lane + 64];
        float gg3 = 0.f, bb3 = 0.f;
        if (lane < 16) { gg3 = ln1g[lane + 96]; bb3 = ln1b[lane + 96]; }
        for (int t = warp; t < 64; t += 14) {
            float* row = Xs + t * XS_STR;
            float v0 = row[lane], v1 = row[lane + 32], v2 = row[lane + 64];
            float v3 = (lane < 16) ? row[lane + 96] : 0.f;
            float s = v0 + v1 + v2 + v3;
            #pragma unroll
            for (int o = 16; o; o >>= 1) s += __shfl_xor_sync(~0u, s, o);
            float m = s * (1.f / 112.f);
            float d0 = v0 - m, d1 = v1 - m, d2 = v2 - m;
            float d3 = (lane < 16) ? v3 - m : 0.f;
            float q = d0*d0 + d1*d1 + d2*d2 + d3*d3;
            #pragma unroll
            for (int o = 16; o; o >>= 1) q += __shfl_xor_sync(~0u, q, o);
            float rs = rsqrtf(q * (1.f / 112.f) + 1e-6f);
            row[lane]      = rtf(d0 * rs * gg0 + bb0);
            row[lane + 32] = rtf(d1 * rs * gg1 + bb1);
            row[lane + 64] = rtf(d2 * rs * gg2 + bb2);
            if (lane < 16) row[lane + 96] = rtf(d3 * rs * gg3 + bb3);
        }
    }
    __syncthreads();

    // ---- QKV+R GEMM: M=64, N=896, K=112; B prefetched one k-step ahead ----
    {
        const unsigned* Xb = (const unsigned*)Xs;
        const unsigned* Wb = (const unsigned*)g_wbig;
        #pragma unroll
        for (int pass = 0; pass < 2; pass++) {
            int colbase = warp * 64 + pass * 32;
            float acc[4][4][4];
            #pragma unroll
            for (int j = 0; j < 4; j++) {
                int col = colbase + j * 8;
                float bv0 = g_bbig[col + 2 * tig];
                float bv1 = g_bbig[col + 2 * tig + 1];
                #pragma unroll
                for (int mt = 0; mt < 4; mt++) {
                    acc[mt][j][0] = bv0; acc[mt][j][1] = bv1;
                    acc[mt][j][2] = bv0; acc[mt][j][3] = bv1;
                }
            }
            // prefetch kc=0 B fragments
            unsigned bc0[4], bc1[4];
            #pragma unroll
            for (int j = 0; j < 4; j++) {
                int col = colbase + j * 8 + g;
                bc0[j] = Wb[tig * 896 + col];
                bc1[j] = Wb[(tig + 4) * 896 + col];
            }
            for (int kc = 0; kc < 112; kc += 8) {
                // prefetch next k-step's B
                unsigned bn0[4], bn1[4];
                int kn = (kc + 8 < 112) ? kc + 8 : kc;
                #pragma unroll
                for (int j = 0; j < 4; j++) {
                    int col = colbase + j * 8 + g;
                    bn0[j] = Wb[(kn + tig) * 896 + col];
                    bn1[j] = Wb[(kn + tig + 4) * 896 + col];
                }
                unsigned a[4][4];
                #pragma unroll
                for (int mt = 0; mt < 4; mt++) {
                    int r0 = (mt * 16 + g) * XS_STR + kc;
                    int r1 = r0 + 8 * XS_STR;
                    a[mt][0] = Xb[r0 + tig];
                    a[mt][1] = Xb[r1 + tig];
                    a[mt][2] = Xb[r0 + tig + 4];
                    a[mt][3] = Xb[r1 + tig + 4];
                }
                #pragma unroll
                for (int j = 0; j < 4; j++) {
                    #pragma unroll
                    for (int mt = 0; mt < 4; mt++)
                        mma_tf32(acc[mt][j], a[mt][0], a[mt][1], a[mt][2], a[mt][3],
                                 bc0[j], bc1[j]);
                }
                #pragma unroll
                for (int j = 0; j < 4; j++) { bc0[j] = bn0[j]; bc1[j] = bn1[j]; }
            }
            // routed stores (uniform branch per warp/j); K and V both row-major float2
            #pragma unroll
            for (int j = 0; j < 4; j++) {
                int col = colbase + j * 8;
                int mat = col / 224;
                int lc  = col - mat * 224;
                if (mat == 1 || mat == 2) {   // K or V -> row-major [t][d]
                    float* dst = (mat == 1) ? Krow : Vrow;
                    int str    = (mat == 1) ? KR_STR : VR_STR;
                    #pragma unroll
                    for (int mt = 0; mt < 4; mt++) {
                        int t0r = mt * 16 + g;
                        *(float2*)&dst[t0r * str + lc + 2*tig] =
                            make_float2(rtf(acc[mt][j][0]), rtf(acc[mt][j][1]));
                        *(float2*)&dst[(t0r + 8) * str + lc + 2*tig] =
                            make_float2(rtf(acc[mt][j][2]), rtf(acc[mt][j][3]));
                    }
                } else {                      // Q (mat 0) or R (mat 3): 2x2 pool in regs
                    #pragma unroll
                    for (int mt = 0; mt < 4; mt++) {
                        float m0 = fmaxf(acc[mt][j][0], acc[mt][j][2]);  // rows g, g+8
                        float m1 = fmaxf(acc[mt][j][1], acc[mt][j][3]);
                        m0 = fmaxf(m0, __shfl_xor_sync(~0u, m0, 4));     // lanes g ^ 1
                        m1 = fmaxf(m1, __shfl_xor_sync(~0u, m1, 4));
                        if (!(g & 1)) {
                            int q = mt * 4 + (g >> 1);
                            if (mat == 0)
                                *(float2*)&Qt[q * QT_STR + lc + 2*tig] =
                                    make_float2(rtf(m0), rtf(m1));
                            else
                                *(float2*)&Rt[q * RT_STR + lc + 2*tig] =
                                    make_float2(m0, m1);
                        }
                    }
                }
            }
        }
    }
    __syncthreads();

    // ---- scores + in-register softmax (8 warps) -> P (aliases Xs) ----
    const float scale = 0.13363062095621219f;   // 56^-0.5
    bool sa = (warp < 8);
    int sh = warp >> 1, snh = warp & 1;
    float sc[4][4];
    if (sa) {
        const unsigned* Qb = (const unsigned*)Qt;
        const unsigned* Kb = (const unsigned*)Krow;
        #pragma unroll
        for (int j = 0; j < 4; j++)
            #pragma unroll
            for (int e = 0; e < 4; e++) sc[j][e] = 0.f;
        #pragma unroll
        for (int kc = 0; kc < 56; kc += 8) {
            int kd = sh * 56 + kc;
            unsigned a0 = Qb[g * QT_STR + kd + tig];
            unsigned a1 = Qb[(g + 8) * QT_STR + kd + tig];
            unsigned a2 = Qb[g * QT_STR + kd + tig + 4];
            unsigned a3 = Qb[(g + 8) * QT_STR + kd + tig + 4];
            #pragma unroll
            for (int j = 0; j < 4; j++) {
                int n0 = snh * 32 + j * 8;
                unsigned b0 = Kb[(n0 + g) * KR_STR + kd + tig];
                unsigned b1 = Kb[(n0 + g) * KR_STR + kd + tig + 4];
                mma_tf32(sc[j], a0, a1, a2, a3, b0, b1);
            }
        }
        // per-warp (half-row) max via quad shuffles
        float m0 = -1e30f, m1 = -1e30f;
        #pragma unroll
        for (int j = 0; j < 4; j++) {
            sc[j][0] *= scale; sc[j][1] *= scale;
            sc[j][2] *= scale; sc[j][3] *= scale;
            m0 = fmaxf(m0, fmaxf(sc[j][0], sc[j][1]));
            m1 = fmaxf(m1, fmaxf(sc[j][2], sc[j][3]));
        }
        m0 = fmaxf(m0, __shfl_xor_sync(~0u, m0, 1));
        m0 = fmaxf(m0, __shfl_xor_sync(~0u, m0, 2));
        m1 = fmaxf(m1, __shfl_xor_sync(~0u, m1, 1));
        m1 = fmaxf(m1, __shfl_xor_sync(~0u, m1, 2));
        if (tig == 0) {
            smax[(sh * 16 + g) * 2 + snh]     = m0;
            smax[(sh * 16 + g + 8) * 2 + snh] = m1;
        }
    }
    __syncthreads();
    if (sa) {
        int r0 = sh * 16 + g, r1 = r0 + 8;
        float M0 = fmaxf(smax[r0 * 2], smax[r0 * 2 + 1]);
        float M1 = fmaxf(smax[r1 * 2], smax[r1 * 2 + 1]);
        float s0 = 0.f, s1 = 0.f;
        #pragma unroll
        for (int j = 0; j < 4; j++) {
            sc[j][0] = __expf(sc[j][0] - M0); sc[j][1] = __expf(sc[j][1] - M0);
            sc[j][2] = __expf(sc[j][2] - M1); sc[j][3] = __expf(sc[j][3] - M1);
            s0 += sc[j][0] + sc[j][1];
            s1 += sc[j][2] + sc[j][3];
        }
        s0 += __shfl_xor_sync(~0u, s0, 1); s0 += __shfl_xor_sync(~0u, s0, 2);
        s1 += __shfl_xor_sync(~0u, s1, 1); s1 += __shfl_xor_sync(~0u, s1, 2);
        if (tig == 0) {
            ssum[r0 * 2 + snh] = s0;
            ssum[r1 * 2 + snh] = s1;
        }
    }
    __syncthreads();
    if (sa) {
        int r0 = sh * 16 + g, r1 = r0 + 8;
        float inv0 = 1.f / (ssum[r0 * 2] + ssum[r0 * 2 + 1]);
        float inv1 = 1.f / (ssum[r1 * 2] + ssum[r1 * 2 + 1]);
        #pragma unroll
        for (int j = 0; j < 4; j++) {
            int n0 = snh * 32 + j * 8;
            *(float2*)&P[r0 * P_STR + n0 + 2*tig] =
                make_float2(rtf(sc[j][0] * inv0), rtf(sc[j][1] * inv0));
            *(float2*)&P[r1 * P_STR + n0 + 2*tig] =
                make_float2(rtf(sc[j][2] * inv1), rtf(sc[j][3] * inv1));
        }
    }
    __syncthreads();

    // ---- PV: per head 16x56x64 -> Ot (aliases Qt) ----
    {
        const unsigned* Pb = (const unsigned*)P;
        const unsigned* Vb = (const unsigned*)Vrow;
        #pragma unroll
        for (int ui = 0; ui < 2; ui++) {
            int u = warp * 2 + ui;        // 0..27
            int h = u / 7, j = u - h * 7;
            int n0 = h * 56 + j * 8;
            float acc[4] = {0.f, 0.f, 0.f, 0.f};
            #pragma unroll
            for (int kc = 0; kc < 64; kc += 8) {
                unsigned a0 = Pb[(h * 16 + g) * P_STR + kc + tig];
                unsigned a1 = Pb[(h * 16 + g + 8) * P_STR + kc + tig];
                unsigned a2 = Pb[(h * 16 + g) * P_STR + kc + tig + 4];
                unsigned a3 = Pb[(h * 16 + g + 8) * P_STR + kc + tig + 4];
                unsigned b0 = Vb[(kc + tig) * VR_STR + n0 + g];
                unsigned b1 = Vb[(kc + tig + 4) * VR_STR + n0 + g];
                mma_tf32(acc, a0, a1, a2, a3, b0, b1);
            }
            *(float2*)&Ot[g * OT_STR + n0 + 2*tig] =
                make_float2(rtf(acc[0]), rtf(acc[1]));
            *(float2*)&Ot[(g + 8) * OT_STR + n0 + 2*tig] =
                make_float2(rtf(acc[2]), rtf(acc[3]));
        }
    }
    __syncthreads();

    // ---- attn_proj (16x224x224), accumulate into Rt ----
    {
        const unsigned* Ob = (const unsigned*)Ot;
        int n0w = warp * 16;
        float acc[2][4];
        #pragma unroll
        for (int j = 0; j < 2; j++) {
            int col = n0w + j * 8;
            float bv0 = bp[col + 2 * tig];
            float bv1 = bp[col + 2 * tig + 1];
            acc[j][0] = bv0; acc[j][1] = bv1; acc[j][2] = bv0; acc[j][3] = bv1;
        }
        #pragma unroll 4
        for (int kc = 0; kc < 224; kc += 8) {
            unsigned a0 = Ob[g * OT_STR + kc + tig];
            unsigned a1 = Ob[(g + 8) * OT_STR + kc + tig];
            unsigned a2 = Ob[g * OT_STR + kc + tig + 4];
            unsigned a3 = Ob[(g + 8) * OT_STR + kc + tig + 4];
            #pragma unroll
            for (int j = 0; j < 2; j++) {
                int n0 = n0w + j * 8;
                unsigned b0 = __float_as_uint(g_wpt[(kc + tig) * 224 + n0 + g]);
                unsigned b1 = __float_as_uint(g_wpt[(kc + tig + 4) * 224 + n0 + g]);
                mma_tf32(acc[j], a0, a1, a2, a3, b0, b1);
            }
        }
        #pragma unroll
        for (int j = 0; j < 2; j++) {
            int d = n0w + j * 8 + 2 * tig;
            float2 r0v = *(float2*)&Rt[g * RT_STR + d];
            *(float2*)&Rt[g * RT_STR + d] =
                make_float2(r0v.x + acc[j][0], r0v.y + acc[j][1]);
            float2 r1v = *(float2*)&Rt[(g + 8) * RT_STR + d];
            *(float2*)&Rt[(g + 8) * RT_STR + d] =
                make_float2(r1v.x + acc[j][2], r1v.y + acc[j][3]);
        }
    }
    __syncthreads();

    // ---- coalesced writeout of hs = residual + proj ----
    for (int e = tid; e < 16 * 56; e += 448) {
        int q = e / 56, c4 = (e - q * 56) * 4;
        int y2 = wy * 4 + (q >> 2), x2 = wx * 4 + (q & 3);
        *(float4*)&g_hs[(((size_t)b * 64 + y2) * 64 + x2) * 224 + c4] =
            *(float4*)&Rt[q * RT_STR + c4];
    }
}

// ---------------------------------------------------------------------------
// K4: out = hs + MLP(LN2(hs)); 512 blocks x 448 threads; W prefetch pipelined
// ---------------------------------------------------------------------------
#define XLN_STR 228
#define HA_STR  452
#define SMEM4   ((64 * XLN_STR + 64 * HA_STR) * 4)   // 174080 B

__global__ void __launch_bounds__(448) k_mlp(
        const float* __restrict__ g2, const float* __restrict__ b2,
        const float* __restrict__ b1, const float* __restrict__ b2m,
        float* __restrict__ out) {
    extern __shared__ float sm[];
    float* Xln = sm;
    float* Ha  = sm + 64 * XLN_STR;

    int t0   = blockIdx.x * 64;
    int tid  = threadIdx.x;
    int warp = tid >> 5, lane = tid & 31;
    int g = lane >> 2, tig = lane & 3;

    {
        float gv[7], bv[7];
        #pragma unroll
        for (int k = 0; k < 7; k++) { gv[k] = g2[lane + 32*k]; bv[k] = b2[lane + 32*k]; }
        for (int t = warp; t < 64; t += 14) {
            const float* hr = &g_hs[(size_t)(t0 + t) * 224];
            float v[7]; float s = 0.f;
            #pragma unroll
            for (int k = 0; k < 7; k++) { v[k] = hr[lane + 32*k]; s += v[k]; }
            #pragma unroll
            for (int o = 16; o; o >>= 1) s += __shfl_xor_sync(~0u, s, o);
            float m = s * (1.f / 224.f);
            float q = 0.f;
            #pragma unroll
            for (int k = 0; k < 7; k++) { v[k] -= m; q += v[k] * v[k]; }
            #pragma unroll
            for (int o = 16; o; o >>= 1) q += __shfl_xor_sync(~0u, q, o);
            float rs = rsqrtf(q * (1.f / 224.f) + 1e-6f);
            #pragma unroll
            for (int k = 0; k < 7; k++)
                Xln[t * XLN_STR + lane + 32*k] = rtf(v[k] * rs * gv[k] + bv[k]);
        }
    }
    __syncthreads();

    const unsigned* Xb = (const unsigned*)Xln;
    const unsigned* Hb = (const unsigned*)Ha;
    const unsigned* W1 = (const unsigned*)g_w1t;
    const unsigned* W2 = (const unsigned*)g_w2t;

    int n0w = warp * 16;
    float acc2[4][2][4];
    #pragma unroll
    for (int j = 0; j < 2; j++) {
        float bv0 = b2m[n0w + j * 8 + 2 * tig];
        float bv1 = b2m[n0w + j * 8 + 2 * tig + 1];
        #pragma unroll
        for (int mt = 0; mt < 4; mt++) {
            acc2[mt][j][0] = bv0; acc2[mt][j][1] = bv1;
            acc2[mt][j][2] = bv0; acc2[mt][j][3] = bv1;
        }
    }

    #pragma unroll 1
    for (int hp = 0; hp < 2; hp++) {
        int hb = hp * 448;
        // ---- MLP1 with pipelined weight prefetch ----
        {
            int cb = hb + warp * 32;
            float acc1[4][4][4];
            #pragma unroll
            for (int j = 0; j < 4; j++) {
                float bv0 = b1[cb + j * 8 + 2 * tig];
                float bv1 = b1[cb + j * 8 + 2 * tig + 1];
                #pragma unroll
                for (int mt = 0; mt < 4; mt++) {
                    acc1[mt][j][0] = bv0; acc1[mt][j][1] = bv1;
                    acc1[mt][j][2] = bv0; acc1[mt][j][3] = bv1;
                }
            }
            unsigned wc0[4], wc1[4];
            #pragma unroll
            for (int j = 0; j < 4; j++) {
                int col = cb + j * 8 + g;
                wc0[j] = W1[tig * 896 + col];
                wc1[j] = W1[(tig + 4) * 896 + col];
            }
            for (int kc = 0; kc < 224; kc += 8) {
                unsigned wn0[4], wn1[4];
                int kn = (kc + 8 < 224) ? kc + 8 : kc;
                #pragma unroll
                for (int j = 0; j < 4; j++) {
                    int col = cb + j * 8 + g;
                    wn0[j] = W1[(kn + tig) * 896 + col];
                    wn1[j] = W1[(kn + tig + 4) * 896 + col];
                }
                unsigned a[4][4];
                #pragma unroll
                for (int mt = 0; mt < 4; mt++) {
                    int r0 = (mt * 16 + g) * XLN_STR + kc;
                    int r1 = r0 + 8 * XLN_STR;
                    a[mt][0] = Xb[r0 + tig];
                    a[mt][1] = Xb[r1 + tig];
                    a[mt][2] = Xb[r0 + tig + 4];
                    a[mt][3] = Xb[r1 + tig + 4];
                }
                #pragma unroll
                for (int j = 0; j < 4; j++)
                    #pragma unroll
                    for (int mt = 0; mt < 4; mt++)
                        mma_tf32(acc1[mt][j], a[mt][0], a[mt][1], a[mt][2], a[mt][3],
                                 wc0[j], wc1[j]);
                #pragma unroll
                for (int j = 0; j < 4; j++) { wc0[j] = wn0[j]; wc1[j] = wn1[j]; }
            }
            int lb = warp * 32;
            #pragma unroll
            for (int mt = 0; mt < 4; mt++)
                #pragma unroll
                for (int j = 0; j < 4; j++) {
                    int lh = lb + j * 8 + 2 * tig;
                    int m0 = mt * 16 + g;
                    float a0 = acc1[mt][j][0], a1 = acc1[mt][j][1];
                    float a2 = acc1[mt][j][2], a3 = acc1[mt][j][3];
                    *(float2*)&Ha[m0 * HA_STR + lh] = make_float2(
                        rtf(0.5f * a0 * (1.f + erff(a0 * 0.70710678118654752f))),
                        rtf(0.5f * a1 * (1.f + erff(a1 * 0.70710678118654752f))));
                    *(float2*)&Ha[(m0 + 8) * HA_STR + lh] = make_float2(
                        rtf(0.5f * a2 * (1.f + erff(a2 * 0.70710678118654752f))),
                        rtf(0.5f * a3 * (1.f + erff(a3 * 0.70710678118654752f))));
                }
        }
        __syncthreads();
        // ---- MLP2 partial over this half (K=448) with pipelined prefetch ----
        {
            unsigned wc0[2], wc1[2];
            #pragma unroll
            for (int j = 0; j < 2; j++) {
                int col = n0w + j * 8 + g;
                wc0[j] = W2[(hb + tig) * 224 + col];
                wc1[j] = W2[(hb + tig + 4) * 224 + col];
            }
            for (int kc = 0; kc < 448; kc += 8) {
                unsigned wn0[2], wn1[2];
                int kn = (kc + 8 < 448) ? kc + 8 : kc;
                #pragma unroll
                for (int j = 0; j < 2; j++) {
                    int col = n0w + j * 8 + g;
                    wn0[j] = W2[(hb + kn + tig) * 224 + col];
                    wn1[j] = W2[(hb + kn + tig + 4) * 224 + col];
                }
                unsigned a[4][4];
                #pragma unroll
                for (int mt = 0; mt < 4; mt++) {
                    int r0 = (mt * 16 + g) * HA_STR + kc;
                    int r1 = r0 + 8 * HA_STR;
                    a[mt][0] = Hb[r0 + tig];
                    a[mt][1] = Hb[r1 + tig];
                    a[mt][2] = Hb[r0 + tig + 4];
                    a[mt][3] = Hb[r1 + tig + 4];
                }
                #pragma unroll
                for (int j = 0; j < 2; j++)
                    #pragma unroll
                    for (int mt = 0; mt < 4; mt++)
                        mma_tf32(acc2[mt][j], a[mt][0], a[mt][1], a[mt][2], a[mt][3],
                                 wc0[j], wc1[j]);
                #pragma unroll
                for (int j = 0; j < 2; j++) { wc0[j] = wn0[j]; wc1[j] = wn1[j]; }
            }
        }
        __syncthreads();
    }

    #pragma unroll
    for (int mt = 0; mt < 4; mt++)
        #pragma unroll
        for (int j = 0; j < 2; j++) {
            int n = n0w + j * 8 + 2 * tig;
            int m0 = t0 + mt * 16 + g;
            float2 h0 = *(const float2*)&g_hs[(size_t)m0 * 224 + n];
            *(float2*)&out[(size_t)m0 * 224 + n] =
                make_float2(h0.x + acc2[mt][j][0], h0.y + acc2[mt][j][1]);
            float2 h1 = *(const float2*)&g_hs[(size_t)(m0 + 8) * 224 + n];
            *(float2*)&out[(size_t)(m0 + 8) * 224 + n] =
                make_float2(h1.x + acc2[mt][j][2], h1.y + acc2[mt][j][3]);
        }
}

// ---------------------------------------------------------------------------
extern "C" void kernel_launch(void* const* d_in, const int* in_sizes, int n_in,
                              void* d_out, int out_size) {
    const float* hidden   = (const float*)d_in[0];
    const float* ln1_g    = (const float*)d_in[1];
    const float* ln1_b    = (const float*)d_in[2];
    const float* qkv_w    = (const float*)d_in[3];
    const float* qkv_b    = (const float*)d_in[4];
    const float* aproj_w  = (const float*)d_in[5];
    const float* aproj_b  = (const float*)d_in[6];
    const float* rproj_w  = (const float*)d_in[7];
    const float* rproj_b  = (const float*)d_in[8];
    const float* ln2_g    = (const float*)d_in[9];
    const float* ln2_b    = (const float*)d_in[10];
    const float* mlp1_w   = (const float*)d_in[11];
    const float* mlp1_b   = (const float*)d_in[12];
    const float* mlp2_w   = (const float*)d_in[13];
    const float* mlp2_b   = (const float*)d_in[14];
    float* out = (float*)d_out;

    cudaFuncSetAttribute(k_attn, cudaFuncAttributeMaxDynamicSharedMemorySize, SMEM3);
    cudaFuncSetAttribute(k_mlp,  cudaFuncAttributeMaxDynamicSharedMemorySize, SMEM4);

    k_prep<<<196, 1024>>>(mlp1_w, mlp2_w, qkv_w, rproj_w, aproj_w, qkv_b, rproj_b);
    k_attn<<<2048, 448, SMEM3>>>(hidden, ln1_g, ln1_b, aproj_b);
    k_mlp<<<512, 448, SMEM4>>>(ln2_g, ln2_b, mlp1_b, mlp2_b, out);
}

// round 17
// speedup vs baseline: 1.5581x; 1.4271x over previous
#include <cuda_runtime.h>
#include <cuda_fp16.h>
#include <math.h>
#include <stdint.h>

#define NTOK  (8*64*64)

// Scratch (device globals)
__device__ float  g_hs[(size_t)NTOK * 224];   // residual + attn output (f32)
__device__ __half g_w1H[896 * 224];           // mlp1_w  [h][c]
__device__ __half g_w2H[224 * 896];           // mlp2_w  [n][h]
__device__ __half g_wbigH[896 * 112];         // [Q|K|V|R] weights [n][k]
__device__ __half g_wpH[224 * 224];           // attn_proj_w [n][k]
__device__ float  g_bbig[896];                // [qkv_b | res_proj_b]

__device__ __forceinline__ void mma_f16(float* c,
        unsigned a0, unsigned a1, unsigned a2, unsigned a3,
        unsigned b0, unsigned b1) {
    asm("mma.sync.aligned.m16n8k16.row.col.f32.f16.f16.f32 "
        "{%0,%1,%2,%3}, {%4,%5,%6,%7}, {%8,%9}, {%0,%1,%2,%3};"
        : "+f"(c[0]), "+f"(c[1]), "+f"(c[2]), "+f"(c[3])
        : "r"(a0), "r"(a1), "r"(a2), "r"(a3), "r"(b0), "r"(b1));
}

__device__ __forceinline__ void sth2(void* p, float a, float b) {
    *(half2*)p = __floats2half2_rn(a, b);
}
__device__ __forceinline__ unsigned packh(__half a, __half b) {
    return (unsigned)__half_as_ushort(a) | ((unsigned)__half_as_ushort(b) << 16);
}

// ---------------------------------------------------------------------------
// K0: convert weights to half in [n][k] transposed layouts + combined bias
// ---------------------------------------------------------------------------
__global__ void k_prep(const float* __restrict__ W1,   const float* __restrict__ W2,
                       const float* __restrict__ Wqkv, const float* __restrict__ Wrp,
                       const float* __restrict__ Wp,
                       const float* __restrict__ bqkv, const float* __restrict__ brp) {
    int i = blockIdx.x * 1024 + threadIdx.x;
    if (i < 224 * 896) {
        int k = i / 896, h = i - k * 896;
        g_w1H[h * 224 + k] = __float2half_rn(W1[i]);
        int h2 = i / 224, n = i - h2 * 224;
        g_w2H[n * 896 + h2] = __float2half_rn(W2[i]);
    }
    if (i < 112 * 896) {
        int r = i / 896, c = i - r * 896;
        float v = (c < 672) ? Wqkv[r * 672 + c] : Wrp[r * 224 + (c - 672)];
        g_wbigH[c * 112 + r] = __float2half_rn(v);
    }
    if (i < 224 * 224) {
        int k = i / 224, n = i - k * 224;
        g_wpH[n * 224 + k] = __float2half_rn(Wp[i]);
    }
    if (i < 896) g_bbig[i] = (i < 672) ? bqkv[i] : brp[i - 672];
}

// ---------------------------------------------------------------------------
// K3: fused LN1 + QKV/R GEMM + pooling + attention + proj + residual (fp16 mma)
// 2048 blocks x 448 threads (14 warps)
// smem (32-bit words): XsW 64x60 | KrW 64x132 | VrW 64x116 | QtW 16x132
//                      | Rt(f32) 16x236 | stats 256
// Stage(f32, 64x116) aliases KrW; P(half,64x72w=36) aliases XsW; Ot aliases QtW.
// Q/K padded per head to 64 dims (zeros) for clean k16 chunks.
// ---------------------------------------------------------------------------
#define XS_WS  60
#define KR_WS  132
#define VR_WS  116
#define VR_STRH 232
#define QT_WS  132
#define RT_STR 236
#define P_WS   36
#define OT_WS  116
#define STG_STR 116
#define XS_NF  (64 * XS_WS)    // 3840
#define KR_NF  (64 * KR_WS)    // 8448
#define VR_NF  (64 * VR_WS)    // 7424
#define QT_NF  (16 * QT_WS)    // 2112
#define RT_NF  (16 * RT_STR)   // 3776
#define SMEM3  ((XS_NF + KR_NF + VR_NF + QT_NF + RT_NF + 256) * 4)  // 103424 B

__global__ void __launch_bounds__(448) k_attn(
        const float* __restrict__ hidden,
        const float* __restrict__ ln1g, const float* __restrict__ ln1b,
        const float* __restrict__ bp) {
    extern __shared__ float smf[];
    unsigned* XsW = (unsigned*)smf;
    unsigned* KrW = XsW + XS_NF;
    unsigned* VrW = KrW + KR_NF;
    unsigned* QtW = VrW + VR_NF;
    float*    Rt  = (float*)(QtW + QT_NF);
    float*    smax = Rt + RT_NF;     // [64][2]
    float*    ssum = smax + 128;     // [64][2]
    float*    Stage = (float*)KrW;   // alias (dead before K/V written)
    unsigned* PW  = XsW;             // alias (X dead after QKV)
    unsigned* OtW = QtW;             // alias (Qt dead after scores)

    int wi = blockIdx.x;
    int b  = wi >> 8;
    int r  = wi & 255;
    int wy = r >> 4, wx = r & 15;
    int tid  = threadIdx.x;
    int warp = tid >> 5, lane = tid & 31;
    int g = lane >> 2, tig = lane & 3;

    // ---- stage raw window f32 into Stage (aliases Krow region) ----
    for (int e = tid; e < 64 * 28; e += 448) {
        int t = e / 28, c4 = (e - t * 28) * 4;
        int y = wy * 8 + (t >> 3), x = wx * 8 + (t & 7);
        *(float4*)&Stage[t * STG_STR + c4] =
            *(const float4*)&hidden[(((size_t)b * 128 + y) * 128 + x) * 112 + c4];
    }
    // zero Qt head-pad columns (words 28..31 per head block)
    if (tid < 256) {
        int t = tid >> 4, i = tid & 15;
        int h = i >> 2, p = i & 3;
        QtW[t * QT_WS + h * 32 + 28 + p] = 0;
    }
    __syncthreads();

    // ---- LN1: warp per token; read Stage f32, write Xs half (pairs) ----
    {
        float gg0 = ln1g[2*lane], gg1 = ln1g[2*lane + 1];
        float bb0 = ln1b[2*lane], bb1 = ln1b[2*lane + 1];
        float gg2 = 0.f, gg3 = 0.f, bb2 = 0.f, bb3 = 0.f;
        if (lane < 24) {
            gg2 = ln1g[64 + 2*lane]; gg3 = ln1g[65 + 2*lane];
            bb2 = ln1b[64 + 2*lane]; bb3 = ln1b[65 + 2*lane];
        }
        for (int t = warp; t < 64; t += 14) {
            float2 p0 = *(const float2*)&Stage[t * STG_STR + 2*lane];
            float2 p1 = make_float2(0.f, 0.f);
            if (lane < 24) p1 = *(const float2*)&Stage[t * STG_STR + 64 + 2*lane];
            float s = p0.x + p0.y + p1.x + p1.y;
            #pragma unroll
            for (int o = 16; o; o >>= 1) s += __shfl_xor_sync(~0u, s, o);
            float m = s * (1.f / 112.f);
            float d0 = p0.x - m, d1 = p0.y - m;
            float d2 = (lane < 24) ? p1.x - m : 0.f;
            float d3 = (lane < 24) ? p1.y - m : 0.f;
            float q = d0*d0 + d1*d1 + d2*d2 + d3*d3;
            #pragma unroll
            for (int o = 16; o; o >>= 1) q += __shfl_xor_sync(~0u, q, o);
            float rs = rsqrtf(q * (1.f / 112.f) + 1e-6f);
            sth2(&((half2*)XsW)[t * XS_WS + lane], d0 * rs * gg0 + bb0, d1 * rs * gg1 + bb1);
            if (lane < 24)
                sth2(&((half2*)XsW)[t * XS_WS + 32 + lane],
                     d2 * rs * gg2 + bb2, d3 * rs * gg3 + bb3);
        }
    }
    __syncthreads();

    // ---- zero Krow head-pad columns (Stage alias now dead) ----
    for (int e = tid; e < 64 * 16; e += 448) {
        int t = e >> 4, i = e & 15;
        int h = i >> 2, p = i & 3;
        KrW[t * KR_WS + h * 32 + 28 + p] = 0;
    }

    // ---- QKV+R GEMM: M=64, N=896, K=112 (7 k16-chunks); B prefetched ----
    {
        const unsigned* WbW = (const unsigned*)g_wbigH;   // word = n*56 + k/2
        #pragma unroll
        for (int pass = 0; pass < 2; pass++) {
            int colbase = warp * 64 + pass * 32;
            float acc[4][4][4];
            #pragma unroll
            for (int j = 0; j < 4; j++) {
                int col = colbase + j * 8;
                float bv0 = g_bbig[col + 2 * tig];
                float bv1 = g_bbig[col + 2 * tig + 1];
                #pragma unroll
                for (int mt = 0; mt < 4; mt++) {
                    acc[mt][j][0] = bv0; acc[mt][j][1] = bv1;
                    acc[mt][j][2] = bv0; acc[mt][j][3] = bv1;
                }
            }
            unsigned bc0[4], bc1[4];
            #pragma unroll
            for (int j = 0; j < 4; j++) {
                int col = colbase + j * 8 + g;
                bc0[j] = WbW[col * 56 + tig];
                bc1[j] = WbW[col * 56 + 4 + tig];
            }
            for (int kc = 0; kc < 112; kc += 16) {
                unsigned bn0[4], bn1[4];
                int kn = (kc + 16 < 112) ? kc + 16 : kc;
                #pragma unroll
                for (int j = 0; j < 4; j++) {
                    int col = colbase + j * 8 + g;
                    bn0[j] = WbW[col * 56 + kn/2 + tig];
                    bn1[j] = WbW[col * 56 + kn/2 + 4 + tig];
                }
                unsigned a[4][4];
                #pragma unroll
                for (int mt = 0; mt < 4; mt++) {
                    int r0 = (mt * 16 + g) * XS_WS + kc/2 + tig;
                    int r1 = r0 + 8 * XS_WS;
                    a[mt][0] = XsW[r0];
                    a[mt][1] = XsW[r1];
                    a[mt][2] = XsW[r0 + 4];
                    a[mt][3] = XsW[r1 + 4];
                }
                #pragma unroll
                for (int j = 0; j < 4; j++)
                    #pragma unroll
                    for (int mt = 0; mt < 4; mt++)
                        mma_f16(acc[mt][j], a[mt][0], a[mt][1], a[mt][2], a[mt][3],
                                bc0[j], bc1[j]);
                #pragma unroll
                for (int j = 0; j < 4; j++) { bc0[j] = bn0[j]; bc1[j] = bn1[j]; }
            }
            // routed epilogues
            #pragma unroll
            for (int j = 0; j < 4; j++) {
                int col = colbase + j * 8;
                int mat = col / 224;
                int lc  = col - mat * 224;
                if (mat == 1) {            // K -> Krow half, head-padded cols
                    int h = lc / 56;
                    int pk = lc + 2 * tig + 8 * h;
                    #pragma unroll
                    for (int mt = 0; mt < 4; mt++) {
                        int t0r = mt * 16 + g;
                        sth2(&((half2*)KrW)[t0r * KR_WS + pk/2],
                             acc[mt][j][0], acc[mt][j][1]);
                        sth2(&((half2*)KrW)[(t0r + 8) * KR_WS + pk/2],
                             acc[mt][j][2], acc[mt][j][3]);
                    }
                } else if (mat == 2) {     // V -> Vrow half [t][d]
                    int pd = lc + 2 * tig;
                    #pragma unroll
                    for (int mt = 0; mt < 4; mt++) {
                        int t0r = mt * 16 + g;
                        sth2(&((half2*)VrW)[t0r * VR_WS + pd/2],
                             acc[mt][j][0], acc[mt][j][1]);
                        sth2(&((half2*)VrW)[(t0r + 8) * VR_WS + pd/2],
                             acc[mt][j][2], acc[mt][j][3]);
                    }
                } else {                   // Q (0) or R (3): 2x2 pool in regs
                    #pragma unroll
                    for (int mt = 0; mt < 4; mt++) {
                        float m0 = fmaxf(acc[mt][j][0], acc[mt][j][2]);
                        float m1 = fmaxf(acc[mt][j][1], acc[mt][j][3]);
                        m0 = fmaxf(m0, __shfl_xor_sync(~0u, m0, 4));
                        m1 = fmaxf(m1, __shfl_xor_sync(~0u, m1, 4));
                        if (!(g & 1)) {
                            int q = mt * 4 + (g >> 1);
                            if (mat == 0) {
                                int h = lc / 56;
                                int pk = lc + 2 * tig + 8 * h;
                                sth2(&((half2*)QtW)[q * QT_WS + pk/2], m0, m1);
                            } else {
                                *(float2*)&Rt[q * RT_STR + lc + 2*tig] =
                                    make_float2(m0, m1);
                            }
                        }
                    }
                }
            }
        }
    }
    __syncthreads();

    // ---- scores (Q Kt, K=64 padded per head) + in-register softmax ----
    const float scale = 0.13363062095621219f;   // 56^-0.5
    bool sa = (warp < 8);
    int sh = warp >> 1, snh = warp & 1;
    float sc[4][4];
    if (sa) {
        #pragma unroll
        for (int j = 0; j < 4; j++)
            #pragma unroll
            for (int e = 0; e < 4; e++) sc[j][e] = 0.f;
        #pragma unroll
        for (int kc = 0; kc < 64; kc += 16) {
            int kb = sh * 32 + kc/2;
            unsigned a0 = QtW[g * QT_WS + kb + tig];
            unsigned a1 = QtW[(g + 8) * QT_WS + kb + tig];
            unsigned a2 = QtW[g * QT_WS + kb + 4 + tig];
            unsigned a3 = QtW[(g + 8) * QT_WS + kb + 4 + tig];
            #pragma unroll
            for (int j = 0; j < 4; j++) {
                int n0 = snh * 32 + j * 8;
                unsigned b0 = KrW[(n0 + g) * KR_WS + kb + tig];
                unsigned b1 = KrW[(n0 + g) * KR_WS + kb + 4 + tig];
                mma_f16(sc[j], a0, a1, a2, a3, b0, b1);
            }
        }
        float m0 = -1e30f, m1 = -1e30f;
        #pragma unroll
        for (int j = 0; j < 4; j++) {
            sc[j][0] *= scale; sc[j][1] *= scale;
            sc[j][2] *= scale; sc[j][3] *= scale;
            m0 = fmaxf(m0, fmaxf(sc[j][0], sc[j][1]));
            m1 = fmaxf(m1, fmaxf(sc[j][2], sc[j][3]));
        }
        m0 = fmaxf(m0, __shfl_xor_sync(~0u, m0, 1));
        m0 = fmaxf(m0, __shfl_xor_sync(~0u, m0, 2));
        m1 = fmaxf(m1, __shfl_xor_sync(~0u, m1, 1));
        m1 = fmaxf(m1, __shfl_xor_sync(~0u, m1, 2));
        if (tig == 0) {
            smax[(sh * 16 + g) * 2 + snh]     = m0;
            smax[(sh * 16 + g + 8) * 2 + snh] = m1;
        }
    }
    __syncthreads();
    if (sa) {
        int r0 = sh * 16 + g, r1 = r0 + 8;
        float M0 = fmaxf(smax[r0 * 2], smax[r0 * 2 + 1]);
        float M1 = fmaxf(smax[r1 * 2], smax[r1 * 2 + 1]);
        float s0 = 0.f, s1 = 0.f;
        #pragma unroll
        for (int j = 0; j < 4; j++) {
            sc[j][0] = __expf(sc[j][0] - M0); sc[j][1] = __expf(sc[j][1] - M0);
            sc[j][2] = __expf(sc[j][2] - M1); sc[j][3] = __expf(sc[j][3] - M1);
            s0 += sc[j][0] + sc[j][1];
            s1 += sc[j][2] + sc[j][3];
        }
        s0 += __shfl_xor_sync(~0u, s0, 1); s0 += __shfl_xor_sync(~0u, s0, 2);
        s1 += __shfl_xor_sync(~0u, s1, 1); s1 += __shfl_xor_sync(~0u, s1, 2);
        if (tig == 0) {
            ssum[r0 * 2 + snh] = s0;
            ssum[r1 * 2 + snh] = s1;
        }
    }
    __syncthreads();
    if (sa) {
        int r0 = sh * 16 + g, r1 = r0 + 8;
        float inv0 = 1.f / (ssum[r0 * 2] + ssum[r0 * 2 + 1]);
        float inv1 = 1.f / (ssum[r1 * 2] + ssum[r1 * 2 + 1]);
        #pragma unroll
        for (int j = 0; j < 4; j++) {
            int n0 = snh * 32 + j * 8;
            sth2(&((half2*)PW)[r0 * P_WS + (n0 + 2*tig)/2],
                 sc[j][0] * inv0, sc[j][1] * inv0);
            sth2(&((half2*)PW)[r1 * P_WS + (n0 + 2*tig)/2],
                 sc[j][2] * inv1, sc[j][3] * inv1);
        }
    }
    __syncthreads();

    // ---- PV: per head 16x56x64 -> Ot half (aliases Qt) ----
    {
        const __half* Vh = (const __half*)VrW;
        #pragma unroll
        for (int ui = 0; ui < 2; ui++) {
            int u = warp * 2 + ui;
            int h = u / 7, j = u - h * 7;
            int n0 = h * 56 + j * 8;
            int n = n0 + g;
            float acc[4] = {0.f, 0.f, 0.f, 0.f};
            #pragma unroll
            for (int kc = 0; kc < 64; kc += 16) {
                unsigned a0 = PW[(h * 16 + g) * P_WS + kc/2 + tig];
                unsigned a1 = PW[(h * 16 + g + 8) * P_WS + kc/2 + tig];
                unsigned a2 = PW[(h * 16 + g) * P_WS + kc/2 + 4 + tig];
                unsigned a3 = PW[(h * 16 + g + 8) * P_WS + kc/2 + 4 + tig];
                unsigned b0 = packh(Vh[(kc + 2*tig) * VR_STRH + n],
                                    Vh[(kc + 2*tig + 1) * VR_STRH + n]);
                unsigned b1 = packh(Vh[(kc + 8 + 2*tig) * VR_STRH + n],
                                    Vh[(kc + 9 + 2*tig) * VR_STRH + n]);
                mma_f16(acc, a0, a1, a2, a3, b0, b1);
            }
            sth2(&((half2*)OtW)[g * OT_WS + (n0 + 2*tig)/2], acc[0], acc[1]);
            sth2(&((half2*)OtW)[(g + 8) * OT_WS + (n0 + 2*tig)/2], acc[2], acc[3]);
        }
    }
    __syncthreads();

    // ---- attn_proj (16x224x224), K=14 k16-chunks, accumulate into Rt ----
    {
        const unsigned* WpW = (const unsigned*)g_wpH;   // word = n*112 + k/2
        int n0w = warp * 16;
        float acc[2][4];
        #pragma unroll
        for (int j = 0; j < 2; j++) {
            int col = n0w + j * 8;
            float bv0 = bp[col + 2 * tig];
            float bv1 = bp[col + 2 * tig + 1];
            acc[j][0] = bv0; acc[j][1] = bv1; acc[j][2] = bv0; acc[j][3] = bv1;
        }
        #pragma unroll 2
        for (int kc = 0; kc < 224; kc += 16) {
            unsigned a0 = OtW[g * OT_WS + kc/2 + tig];
            unsigned a1 = OtW[(g + 8) * OT_WS + kc/2 + tig];
            unsigned a2 = OtW[g * OT_WS + kc/2 + 4 + tig];
            unsigned a3 = OtW[(g + 8) * OT_WS + kc/2 + 4 + tig];
            #pragma unroll
            for (int j = 0; j < 2; j++) {
                int col = n0w + j * 8 + g;
                unsigned b0 = WpW[col * 112 + kc/2 + tig];
                unsigned b1 = WpW[col * 112 + kc/2 + 4 + tig];
                mma_f16(acc[j], a0, a1, a2, a3, b0, b1);
            }
        }
        #pragma unroll
        for (int j = 0; j < 2; j++) {
            int d = n0w + j * 8 + 2 * tig;
            float2 r0v = *(float2*)&Rt[g * RT_STR + d];
            *(float2*)&Rt[g * RT_STR + d] =
                make_float2(r0v.x + acc[j][0], r0v.y + acc[j][1]);
            float2 r1v = *(float2*)&Rt[(g + 8) * RT_STR + d];
            *(float2*)&Rt[(g + 8) * RT_STR + d] =
                make_float2(r1v.x + acc[j][2], r1v.y + acc[j][3]);
        }
    }
    __syncthreads();

    // ---- coalesced writeout of hs = residual + proj ----
    for (int e = tid; e < 16 * 56; e += 448) {
        int q = e / 56, c4 = (e - q * 56) * 4;
        int y2 = wy * 4 + (q >> 2), x2 = wx * 4 + (q & 3);
        *(float4*)&g_hs[(((size_t)b * 64 + y2) * 64 + x2) * 224 + c4] =
            *(float4*)&Rt[q * RT_STR + c4];
    }
}

// ---------------------------------------------------------------------------
// K4: out = hs + MLP(LN2(hs)); 512 blocks x 448 threads; fp16 mma + prefetch
// smem (words): XlnW 64x116 | HaW 64x452
// ---------------------------------------------------------------------------
#define XLN_WS 116
#define HA_WS  452
#define SMEM4  ((64 * XLN_WS + 64 * HA_WS) * 4)   // 145408 B

__global__ void __launch_bounds__(448) k_mlp(
        const float* __restrict__ g2, const float* __restrict__ b2,
        const float* __restrict__ b1, const float* __restrict__ b2m,
        float* __restrict__ out) {
    extern __shared__ float smf[];
    unsigned* XlnW = (unsigned*)smf;
    unsigned* HaW  = XlnW + 64 * XLN_WS;

    int t0   = blockIdx.x * 64;
    int tid  = threadIdx.x;
    int warp = tid >> 5, lane = tid & 31;
    int g = lane >> 2, tig = lane & 3;

    // ---- LN2 (warp per token, channel pairs) -> Xln half ----
    {
        float gv[8], bv[8];
        #pragma unroll
        for (int k = 0; k < 3; k++) {
            gv[2*k]   = g2[2*lane + 64*k];     gv[2*k+1] = g2[2*lane + 64*k + 1];
            bv[2*k]   = b2[2*lane + 64*k];     bv[2*k+1] = b2[2*lane + 64*k + 1];
        }
        gv[6] = gv[7] = bv[6] = bv[7] = 0.f;
        if (lane < 16) {
            gv[6] = g2[2*lane + 192]; gv[7] = g2[2*lane + 193];
            bv[6] = b2[2*lane + 192]; bv[7] = b2[2*lane + 193];
        }
        for (int t = warp; t < 64; t += 14) {
            const float* hr = &g_hs[(size_t)(t0 + t) * 224];
            float2 p[4];
            #pragma unroll
            for (int k = 0; k < 3; k++) p[k] = *(const float2*)&hr[2*lane + 64*k];
            p[3] = make_float2(0.f, 0.f);
            if (lane < 16) p[3] = *(const float2*)&hr[2*lane + 192];
            float s = 0.f;
            #pragma unroll
            for (int k = 0; k < 4; k++) s += p[k].x + p[k].y;
            #pragma unroll
            for (int o = 16; o; o >>= 1) s += __shfl_xor_sync(~0u, s, o);
            float m = s * (1.f / 224.f);
            float d[8]; float q = 0.f;
            #pragma unroll
            for (int k = 0; k < 4; k++) {
                d[2*k]   = p[k].x - m;
                d[2*k+1] = p[k].y - m;
            }
            if (lane >= 16) { d[6] = 0.f; d[7] = 0.f; }
            #pragma unroll
            for (int k = 0; k < 8; k++) q += d[k] * d[k];
            #pragma unroll
            for (int o = 16; o; o >>= 1) q += __shfl_xor_sync(~0u, q, o);
            float rs = rsqrtf(q * (1.f / 224.f) + 1e-6f);
            #pragma unroll
            for (int k = 0; k < 3; k++)
                sth2(&((half2*)XlnW)[t * XLN_WS + lane + 32*k],
                     d[2*k] * rs * gv[2*k] + bv[2*k],
                     d[2*k+1] * rs * gv[2*k+1] + bv[2*k+1]);
            if (lane < 16)
                sth2(&((half2*)XlnW)[t * XLN_WS + lane + 96],
                     d[6] * rs * gv[6] + bv[6], d[7] * rs * gv[7] + bv[7]);
        }
    }
    __syncthreads();

    const unsigned* W1W = (const unsigned*)g_w1H;   // word = h*112 + c/2
    const unsigned* W2W = (const unsigned*)g_w2H;   // word = n*448 + h/2

    int n0w = warp * 16;
    float acc2[4][2][4];
    #pragma unroll
    for (int j = 0; j < 2; j++) {
        float bv0 = b2m[n0w + j * 8 + 2 * tig];
        float bv1 = b2m[n0w + j * 8 + 2 * tig + 1];
        #pragma unroll
        for (int mt = 0; mt < 4; mt++) {
            acc2[mt][j][0] = bv0; acc2[mt][j][1] = bv1;
            acc2[mt][j][2] = bv0; acc2[mt][j][3] = bv1;
        }
    }

    #pragma unroll 1
    for (int hp = 0; hp < 2; hp++) {
        int hb = hp * 448;
        // ---- MLP1 (K=224, 14 k16-chunks) with pipelined weight prefetch ----
        {
            int cb = hb + warp * 32;
            float acc1[4][4][4];
            #pragma unroll
            for (int j = 0; j < 4; j++) {
                float bv0 = b1[cb + j * 8 + 2 * tig];
                float bv1 = b1[cb + j * 8 + 2 * tig + 1];
                #pragma unroll
                for (int mt = 0; mt < 4; mt++) {
                    acc1[mt][j][0] = bv0; acc1[mt][j][1] = bv1;
                    acc1[mt][j][2] = bv0; acc1[mt][j][3] = bv1;
                }
            }
            unsigned wc0[4], wc1[4];
            #pragma unroll
            for (int j = 0; j < 4; j++) {
                int col = cb + j * 8 + g;
                wc0[j] = W1W[col * 112 + tig];
                wc1[j] = W1W[col * 112 + 4 + tig];
            }
            for (int kc = 0; kc < 224; kc += 16) {
                unsigned wn0[4], wn1[4];
                int kn = (kc + 16 < 224) ? kc + 16 : kc;
                #pragma unroll
                for (int j = 0; j < 4; j++) {
                    int col = cb + j * 8 + g;
                    wn0[j] = W1W[col * 112 + kn/2 + tig];
                    wn1[j] = W1W[col * 112 + kn/2 + 4 + tig];
                }
                unsigned a[4][4];
                #pragma unroll
                for (int mt = 0; mt < 4; mt++) {
                    int r0 = (mt * 16 + g) * XLN_WS + kc/2 + tig;
                    int r1 = r0 + 8 * XLN_WS;
                    a[mt][0] = XlnW[r0];
                    a[mt][1] = XlnW[r1];
                    a[mt][2] = XlnW[r0 + 4];
                    a[mt][3] = XlnW[r1 + 4];
                }
                #pragma unroll
                for (int j = 0; j < 4; j++)
                    #pragma unroll
                    for (int mt = 0; mt < 4; mt++)
                        mma_f16(acc1[mt][j], a[mt][0], a[mt][1], a[mt][2], a[mt][3],
                                wc0[j], wc1[j]);
                #pragma unroll
                for (int j = 0; j < 4; j++) { wc0[j] = wn0[j]; wc1[j] = wn1[j]; }
            }
            int lb = warp * 32;
            #pragma unroll
            for (int mt = 0; mt < 4; mt++)
                #pragma unroll
                for (int j = 0; j < 4; j++) {
                    int lh = lb + j * 8 + 2 * tig;
                    int m0 = mt * 16 + g;
                    float a0 = acc1[mt][j][0], a1 = acc1[mt][j][1];
                    float a2 = acc1[mt][j][2], a3 = acc1[mt][j][3];
                    sth2(&((half2*)HaW)[m0 * HA_WS + lh/2],
                         0.5f * a0 * (1.f + erff(a0 * 0.70710678118654752f)),
                         0.5f * a1 * (1.f + erff(a1 * 0.70710678118654752f)));
                    sth2(&((half2*)HaW)[(m0 + 8) * HA_WS + lh/2],
                         0.5f * a2 * (1.f + erff(a2 * 0.70710678118654752f)),
                         0.5f * a3 * (1.f + erff(a3 * 0.70710678118654752f)));
                }
        }
        __syncthreads();
        // ---- MLP2 partial over this half (K=448, 28 chunks), prefetched ----
        {
            unsigned wc0[2], wc1[2];
            #pragma unroll
            for (int j = 0; j < 2; j++) {
                int col = n0w + j * 8 + g;
                wc0[j] = W2W[col * 448 + hb/2 + tig];
                wc1[j] = W2W[col * 448 + hb/2 + 4 + tig];
            }
            for (int kc = 0; kc < 448; kc += 16) {
                unsigned wn0[2], wn1[2];
                int kn = (kc + 16 < 448) ? kc + 16 : kc;
                #pragma unroll
                for (int j = 0; j < 2; j++) {
                    int col = n0w + j * 8 + g;
                    wn0[j] = W2W[col * 448 + (hb + kn)/2 + tig];
                    wn1[j] = W2W[col * 448 + (hb + kn)/2 + 4 + tig];
                }
                unsigned a[4][4];
                #pragma unroll
                for (int mt = 0; mt < 4; mt++) {
                    int r0 = (mt * 16 + g) * HA_WS + kc/2 + tig;
                    int r1 = r0 + 8 * HA_WS;
                    a[mt][0] = HaW[r0];
                    a[mt][1] = HaW[r1];
                    a[mt][2] = HaW[r0 + 4];
                    a[mt][3] = HaW[r1 + 4];
                }
                #pragma unroll
                for (int j = 0; j < 2; j++)
                    #pragma unroll
                    for (int mt = 0; mt < 4; mt++)
                        mma_f16(acc2[mt][j], a[mt][0], a[mt][1], a[mt][2], a[mt][3],
                                wc0[j], wc1[j]);
                #pragma unroll
                for (int j = 0; j < 2; j++) { wc0[j] = wn0[j]; wc1[j] = wn1[j]; }
            }
        }
        __syncthreads();
    }

    // ---- epilogue: residual + direct store ----
    #pragma unroll
    for (int mt = 0; mt < 4; mt++)
        #pragma unroll
        for (int j = 0; j < 2; j++) {
            int n = n0w + j * 8 + 2 * tig;
            int m0 = t0 + mt * 16 + g;
            float2 h0 = *(const float2*)&g_hs[(size_t)m0 * 224 + n];
            *(float2*)&out[(size_t)m0 * 224 + n] =
                make_float2(h0.x + acc2[mt][j][0], h0.y + acc2[mt][j][1]);
            float2 h1 = *(const float2*)&g_hs[(size_t)(m0 + 8) * 224 + n];
            *(float2*)&out[(size_t)(m0 + 8) * 224 + n] =
                make_float2(h1.x + acc2[mt][j][2], h1.y + acc2[mt][j][3]);
        }
}

// ---------------------------------------------------------------------------
extern "C" void kernel_launch(void* const* d_in, const int* in_sizes, int n_in,
                              void* d_out, int out_size) {
    const float* hidden   = (const float*)d_in[0];
    const float* ln1_g    = (const float*)d_in[1];
    const float* ln1_b    = (const float*)d_in[2];
    const float* qkv_w    = (const float*)d_in[3];
    const float* qkv_b    = (const float*)d_in[4];
    const float* aproj_w  = (const float*)d_in[5];
    const float* aproj_b  = (const float*)d_in[6];
    const float* rproj_w  = (const float*)d_in[7];
    const float* rproj_b  = (const float*)d_in[8];
    const float* ln2_g    = (const float*)d_in[9];
    const float* ln2_b    = (const float*)d_in[10];
    const float* mlp1_w   = (const float*)d_in[11];
    const float* mlp1_b   = (const float*)d_in[12];
    const float* mlp2_w   = (const float*)d_in[13];
    const float* mlp2_b   = (const float*)d_in[14];
    float* out = (float*)d_out;

    cudaFuncSetAttribute(k_attn, cudaFuncAttributeMaxDynamicSharedMemorySize, SMEM3);
    cudaFuncSetAttribute(k_mlp,  cudaFuncAttributeMaxDynamicSharedMemorySize, SMEM4);

    k_prep<<<196, 1024>>>(mlp1_w, mlp2_w, qkv_w, rproj_w, aproj_w, qkv_b, rproj_b);
    k_attn<<<2048, 448, SMEM3>>>(hidden, ln1_g, ln1_b, aproj_b);
    k_mlp<<<512, 448, SMEM4>>>(ln2_g, ln2_b, mlp1_b, mlp2_b, out);
}